// round 1
// baseline (speedup 1.0000x reference)
#include <cuda_runtime.h>
#include <cstdint>
#include <cstdio>

// Problem constants
#define B_WIN   4096
#define NTOK    49
#define CDIM    512
#define NHEAD   16
#define HDIM    32
#define NWMASK  64
#define MTOT    (B_WIN * NTOK)          // 200704
#define QKVN    (3 * CDIM)              // 1536

// Static scratch (allocation-guard-safe)
__device__ float g_qkv [(size_t)MTOT * QKVN];   // [M, 1536]
__device__ float g_attn[(size_t)MTOT * CDIM];   // [M, 512] attention output (B_,N,C layout)
__device__ float g_bias[NHEAD * NTOK * NTOK];   // [H, 49, 49]

// ---------------------------------------------------------------------------
// Kernel 0: precompute relative-position bias per head: bias[h,i,j] = table[idx[i,j], h]
// ---------------------------------------------------------------------------
__global__ void bias_precompute(const float* __restrict__ table,
                                const int*   __restrict__ idx,
                                float*       __restrict__ bias)
{
    int i = blockIdx.x * blockDim.x + threadIdx.x;      // over 49*49
    if (i >= NTOK * NTOK) return;
    int id = idx[i];
    #pragma unroll
    for (int h = 0; h < NHEAD; h++)
        bias[h * (NTOK * NTOK) + i] = table[id * NHEAD + h];
}

// ---------------------------------------------------------------------------
// Kernel 1/3: fp32 SGEMM  C[M,N] = A[M,K] @ B[K,N] + bias[N]
// BM=BN=128, BK=8, 256 threads, 8x8 per-thread micro-tile.
// Requires M%128==0, N%128==0, K%8==0 (all true here).
// ---------------------------------------------------------------------------
__global__ void __launch_bounds__(256)
sgemm128_bias(const float* __restrict__ A, const float* __restrict__ B,
              const float* __restrict__ bias, float* __restrict__ C,
              int N, int K)
{
    __shared__ float As[8][128];
    __shared__ float Bs[8][128];

    const int brow = blockIdx.y * 128;
    const int bcol = blockIdx.x * 128;
    const int tid  = threadIdx.x;
    const int tx   = tid & 15;          // 0..15
    const int ty   = tid >> 4;          // 0..15

    // A loading map: each thread one float4 (128 rows x 8 cols)
    const int a_row = tid >> 1;         // 0..127
    const int a_col = (tid & 1) * 4;    // 0 or 4
    // B loading map: each thread one float4 (8 rows x 128 cols)
    const int b_row = tid >> 5;         // 0..7
    const int b_col = (tid & 31) * 4;   // 0..124

    const float* Aptr = A + (size_t)(brow + a_row) * K + a_col;
    const float* Bptr = B + (size_t)b_row * N + bcol + b_col;

    float acc[8][8];
    #pragma unroll
    for (int i = 0; i < 8; i++)
        #pragma unroll
        for (int j = 0; j < 8; j++) acc[i][j] = 0.f;

    for (int k0 = 0; k0 < K; k0 += 8) {
        float4 a4 = *(const float4*)(Aptr + k0);
        As[a_col + 0][a_row] = a4.x;
        As[a_col + 1][a_row] = a4.y;
        As[a_col + 2][a_row] = a4.z;
        As[a_col + 3][a_row] = a4.w;
        float4 b4 = *(const float4*)(Bptr + (size_t)k0 * N);
        *(float4*)&Bs[b_row][b_col] = b4;
        __syncthreads();

        #pragma unroll
        for (int kk = 0; kk < 8; kk++) {
            float ar[8], br[8];
            *(float4*)(ar + 0) = *(const float4*)&As[kk][ty * 8 + 0];
            *(float4*)(ar + 4) = *(const float4*)&As[kk][ty * 8 + 4];
            *(float4*)(br + 0) = *(const float4*)&Bs[kk][tx * 8 + 0];
            *(float4*)(br + 4) = *(const float4*)&Bs[kk][tx * 8 + 4];
            #pragma unroll
            for (int i = 0; i < 8; i++)
                #pragma unroll
                for (int j = 0; j < 8; j++)
                    acc[i][j] += ar[i] * br[j];
        }
        __syncthreads();
    }

    // epilogue: add bias, store
    #pragma unroll
    for (int i = 0; i < 8; i++) {
        const size_t r = (size_t)(brow + ty * 8 + i);
        #pragma unroll
        for (int j = 0; j < 8; j += 4) {
            const int c = bcol + tx * 8 + j;
            float4 o;
            o.x = acc[i][j + 0] + bias[c + 0];
            o.y = acc[i][j + 1] + bias[c + 1];
            o.z = acc[i][j + 2] + bias[c + 2];
            o.w = acc[i][j + 3] + bias[c + 3];
            *(float4*)&C[r * N + c] = o;
        }
    }
}

// ---------------------------------------------------------------------------
// Kernel 2: window attention. One block per (b, h). 128 threads (4 warps).
//   attn = softmax(scale*q@k^T + bias[h] + mask[b%64]);  out = attn @ v
// q/k/v read from g_qkv[M,1536] columns {0,512,1024} + h*32.
// Output written directly in [B_, N, C] layout for the proj GEMM.
// ---------------------------------------------------------------------------
__global__ void __launch_bounds__(128)
window_attn(const float* __restrict__ qkv, const float* __restrict__ mask,
            const float* __restrict__ bias, float* __restrict__ out)
{
    const int b = blockIdx.x;
    const int h = blockIdx.y;

    __shared__ float qs[NTOK * 33];
    __shared__ float ks[NTOK * 33];
    __shared__ float vs[NTOK * 33];
    __shared__ float ps[4][64];

    const float scale = 0.1767766952966369f;  // 1/sqrt(32)
    const int tid = threadIdx.x;

    // load q (pre-scaled), k, v tiles
    const float* base = qkv + (size_t)b * NTOK * QKVN + h * HDIM;
    for (int i = tid; i < NTOK * HDIM; i += 128) {
        const int n = i >> 5, d = i & 31;
        const float* row = base + (size_t)n * QKVN + d;
        qs[n * 33 + d] = row[0] * scale;
        ks[n * 33 + d] = row[CDIM];
        vs[n * 33 + d] = row[2 * CDIM];
    }
    __syncthreads();

    const int warp = tid >> 5;
    const int lane = tid & 31;
    const float* mrow = mask + (size_t)(b & (NWMASK - 1)) * NTOK * NTOK;
    const float* brow = bias + (size_t)h * NTOK * NTOK;

    for (int r = warp; r < NTOK; r += 4) {
        // ---- scores: lane handles columns lane and lane+32 ----
        const int   c1    = lane + 32;
        const bool  v1    = (c1 < NTOK);               // lanes 0..16
        const float* krow0 = ks + lane * 33;
        const float* krow1 = ks + (v1 ? c1 : 0) * 33;
        const float* qrow  = qs + r * 33;
        float a0 = 0.f, a1 = 0.f;
        #pragma unroll
        for (int dd = 0; dd < HDIM; dd++) {
            const float qv = qrow[dd];
            a0 += qv * krow0[dd];
            a1 += qv * krow1[dd];
        }
        a0 += brow[r * NTOK + lane] + mrow[r * NTOK + lane];
        if (v1) a1 += brow[r * NTOK + c1] + mrow[r * NTOK + c1];

        // ---- softmax over 49 cols ----
        float mx = fmaxf(a0, v1 ? a1 : -1e30f);
        #pragma unroll
        for (int o = 16; o > 0; o >>= 1)
            mx = fmaxf(mx, __shfl_xor_sync(0xffffffffu, mx, o));
        const float e0 = __expf(a0 - mx);
        const float e1 = v1 ? __expf(a1 - mx) : 0.f;
        float s = e0 + e1;
        #pragma unroll
        for (int o = 16; o > 0; o >>= 1)
            s += __shfl_xor_sync(0xffffffffu, s, o);
        const float inv = 1.f / s;
        ps[warp][lane] = e0 * inv;
        if (v1) ps[warp][c1] = e1 * inv;
        __syncwarp();

        // ---- out[r][d] = sum_m p[m] * v[m][d];  lane == d ----
        float o = 0.f;
        #pragma unroll 7
        for (int m = 0; m < NTOK; m++)
            o += ps[warp][m] * vs[m * 33 + lane];
        out[((size_t)b * NTOK + r) * CDIM + h * HDIM + lane] = o;
        __syncwarp();
    }
}

// ---------------------------------------------------------------------------
// Host launcher
// ---------------------------------------------------------------------------
extern "C" void kernel_launch(void* const* d_in, const int* in_sizes, int n_in,
                              void* d_out, int out_size)
{
    const float* x       = (const float*)d_in[0];
    const float* mask    = (const float*)d_in[1];
    const float* qkv_w   = (const float*)d_in[2];
    const float* qkv_b   = (const float*)d_in[3];
    const float* proj_w  = (const float*)d_in[4];
    const float* proj_b  = (const float*)d_in[5];
    const float* table   = (const float*)d_in[6];
    const int*   rpi     = (const int*)  d_in[7];
    float*       out     = (float*)d_out;

    float *qkv, *attn, *bias;
    cudaGetSymbolAddress((void**)&qkv,  g_qkv);
    cudaGetSymbolAddress((void**)&attn, g_attn);
    cudaGetSymbolAddress((void**)&bias, g_bias);

    // 0) bias precompute
    bias_precompute<<<(NTOK * NTOK + 127) / 128, 128>>>(table, rpi, bias);

    // 1) QKV GEMM: [M,512] @ [512,1536] + b  -> g_qkv
    {
        dim3 grid(QKVN / 128, MTOT / 128);
        sgemm128_bias<<<grid, 256>>>(x, qkv_w, qkv_b, qkv, QKVN, CDIM);
    }

    // 2) attention per (b, h) -> g_attn in [B_, N, C] layout
    {
        dim3 grid(B_WIN, NHEAD);
        window_attn<<<grid, 128>>>(qkv, mask, bias, attn);
    }

    // 3) proj GEMM: [M,512] @ [512,512] + b -> d_out
    {
        dim3 grid(CDIM / 128, MTOT / 128);
        sgemm128_bias<<<grid, 256>>>(attn, proj_w, proj_b, out, CDIM, CDIM);
    }
}